// round 4
// baseline (speedup 1.0000x reference)
#include <cuda_runtime.h>

#define EPS 1e-6f

// x: (2048, 4096, 16) fp32  -> 8,388,608 rows of 16 floats (64 B each)
// Grade slices over last dim: [0,1) [1,5) [5,11) [11,15) [15,16)
// out[..., a:b] = x[..., a:b] * rsqrt(sum(x[a:b]^2) + eps) * scale[g]
//
// Streaming kernel: .cs (evict-first) hints on both streams, 2 rows/thread
// for MLP=8 and half the wave count.

__device__ __forceinline__ void process_row(const float4* __restrict__ x,
                                            float4* __restrict__ out,
                                            size_t base,
                                            float sc0, float sc1, float sc2,
                                            float sc3, float sc4)
{
    float4 a = __ldcs(&x[base + 0]);
    float4 b = __ldcs(&x[base + 1]);
    float4 c = __ldcs(&x[base + 2]);
    float4 d = __ldcs(&x[base + 3]);

    float s0 = a.x * a.x;
    float s1 = a.y * a.y + a.z * a.z + a.w * a.w + b.x * b.x;
    float s2 = b.y * b.y + b.z * b.z + b.w * b.w
             + c.x * c.x + c.y * c.y + c.z * c.z;
    float s3 = c.w * c.w + d.x * d.x + d.y * d.y + d.z * d.z;
    float s4 = d.w * d.w;

    float r0 = rsqrtf(s0 + EPS) * sc0;
    float r1 = rsqrtf(s1 + EPS) * sc1;
    float r2 = rsqrtf(s2 + EPS) * sc2;
    float r3 = rsqrtf(s3 + EPS) * sc3;
    float r4 = rsqrtf(s4 + EPS) * sc4;

    float4 oa, ob, oc, od;
    oa.x = a.x * r0;
    oa.y = a.y * r1;  oa.z = a.z * r1;  oa.w = a.w * r1;
    ob.x = b.x * r1;
    ob.y = b.y * r2;  ob.z = b.z * r2;  ob.w = b.w * r2;
    oc.x = c.x * r2;  oc.y = c.y * r2;  oc.z = c.z * r2;
    oc.w = c.w * r3;
    od.x = d.x * r3;  od.y = d.y * r3;  od.z = d.z * r3;
    od.w = d.w * r4;

    __stcs(&out[base + 0], oa);
    __stcs(&out[base + 1], ob);
    __stcs(&out[base + 2], oc);
    __stcs(&out[base + 3], od);
}

__global__ void __launch_bounds__(256)
gradewise_ln_kernel(const float4* __restrict__ x,
                    const float*  __restrict__ scale,
                    float4* __restrict__ out,
                    int nrows)
{
    // Each block handles 512 consecutive rows: thread t does rows
    // blockIdx*512 + t and blockIdx*512 + 256 + t (both warp-coalesced).
    int row0 = blockIdx.x * (blockDim.x * 2) + threadIdx.x;
    int row1 = row0 + blockDim.x;

    float sc0 = __ldg(&scale[0]);
    float sc1 = __ldg(&scale[1]);
    float sc2 = __ldg(&scale[2]);
    float sc3 = __ldg(&scale[3]);
    float sc4 = __ldg(&scale[4]);

    if (row0 < nrows)
        process_row(x, out, (size_t)row0 * 4, sc0, sc1, sc2, sc3, sc4);
    if (row1 < nrows)
        process_row(x, out, (size_t)row1 * 4, sc0, sc1, sc2, sc3, sc4);
}

extern "C" void kernel_launch(void* const* d_in, const int* in_sizes, int n_in,
                              void* d_out, int out_size)
{
    const float4* x     = (const float4*)d_in[0];
    const float*  scale = (const float*)d_in[1];
    float4*       out   = (float4*)d_out;

    int nrows = in_sizes[0] / 16;  // 2048*4096 = 8,388,608

    const int threads = 256;
    const int rows_per_block = threads * 2;
    int blocks = (nrows + rows_per_block - 1) / rows_per_block;

    gradewise_ln_kernel<<<blocks, threads>>>(x, scale, out, nrows);
}

// round 5
// speedup vs baseline: 1.0825x; 1.0825x over previous
#include <cuda_runtime.h>

#define EPS 1e-6f

// x: (2048, 4096, 16) fp32  -> 8,388,608 rows of 16 floats (64 B each)
// Grade slices over last dim: [0,1) [1,5) [5,11) [11,15) [15,16)
// out[..., a:b] = x[..., a:b] * rsqrt(sum(x[a:b]^2) + eps) * scale[g]
//
// Pure HBM-streaming kernel. sm_103a 256-bit global ld/st: each row is
// 2x ld.global.nc.v8.f32 + 2x st.global.v8.f32 (vs 4+4 128-bit), halving
// LSU wavefronts and lengthening DRAM bursts.

__device__ __forceinline__ void ld256(const float* __restrict__ p, float* r)
{
    asm volatile("ld.global.nc.v8.f32 {%0,%1,%2,%3,%4,%5,%6,%7}, [%8];"
                 : "=f"(r[0]), "=f"(r[1]), "=f"(r[2]), "=f"(r[3]),
                   "=f"(r[4]), "=f"(r[5]), "=f"(r[6]), "=f"(r[7])
                 : "l"(p));
}

__device__ __forceinline__ void st256(float* __restrict__ p, const float* r)
{
    asm volatile("st.global.v8.f32 [%0], {%1,%2,%3,%4,%5,%6,%7,%8};"
                 :: "l"(p),
                    "f"(r[0]), "f"(r[1]), "f"(r[2]), "f"(r[3]),
                    "f"(r[4]), "f"(r[5]), "f"(r[6]), "f"(r[7])
                 : "memory");
}

__global__ void __launch_bounds__(256)
gradewise_ln_kernel(const float* __restrict__ x,
                    const float* __restrict__ scale,
                    float*       __restrict__ out,
                    int nrows)
{
    int row = blockIdx.x * blockDim.x + threadIdx.x;
    if (row >= nrows) return;

    size_t base = (size_t)row * 16;

    float v[16];
    ld256(x + base,     v);
    ld256(x + base + 8, v + 8);

    // grade sums of squares over slices [0,1) [1,5) [5,11) [11,15) [15,16)
    float s0 = v[0] * v[0];
    float s1 = v[1] * v[1] + v[2] * v[2] + v[3] * v[3] + v[4] * v[4];
    float s2 = v[5] * v[5] + v[6] * v[6] + v[7] * v[7]
             + v[8] * v[8] + v[9] * v[9] + v[10] * v[10];
    float s3 = v[11] * v[11] + v[12] * v[12] + v[13] * v[13] + v[14] * v[14];
    float s4 = v[15] * v[15];

    float r0 = rsqrtf(s0 + EPS) * __ldg(&scale[0]);
    float r1 = rsqrtf(s1 + EPS) * __ldg(&scale[1]);
    float r2 = rsqrtf(s2 + EPS) * __ldg(&scale[2]);
    float r3 = rsqrtf(s3 + EPS) * __ldg(&scale[3]);
    float r4 = rsqrtf(s4 + EPS) * __ldg(&scale[4]);

    float o[16];
    o[0]  = v[0]  * r0;
    o[1]  = v[1]  * r1;  o[2]  = v[2]  * r1;  o[3]  = v[3]  * r1;
    o[4]  = v[4]  * r1;
    o[5]  = v[5]  * r2;  o[6]  = v[6]  * r2;  o[7]  = v[7]  * r2;
    o[8]  = v[8]  * r2;  o[9]  = v[9]  * r2;  o[10] = v[10] * r2;
    o[11] = v[11] * r3;  o[12] = v[12] * r3;  o[13] = v[13] * r3;
    o[14] = v[14] * r3;
    o[15] = v[15] * r4;

    st256(out + base,     o);
    st256(out + base + 8, o + 8);
}

extern "C" void kernel_launch(void* const* d_in, const int* in_sizes, int n_in,
                              void* d_out, int out_size)
{
    const float* x     = (const float*)d_in[0];
    const float* scale = (const float*)d_in[1];
    float*       out   = (float*)d_out;

    int nrows = in_sizes[0] / 16;  // 2048*4096 = 8,388,608

    const int threads = 256;
    int blocks = (nrows + threads - 1) / threads;

    gradewise_ln_kernel<<<blocks, threads>>>(x, scale, out, nrows);
}